// round 1
// baseline (speedup 1.0000x reference)
#include <cuda_runtime.h>
#include <cuda_bf16.h>
#include <math.h>

// Problem constants (fixed shapes for this problem)
#define NN 50000
#define EE 300000
#define DD 256
#define FF 1024
#define CC 40

// ---------------- scratch (device globals; no allocation allowed) ----------------
__device__ float g_norms[NN];         // out-degree norm (src side)
__device__ float g_normd[NN];         // in-degree norm (dst side)
__device__ float g_XA[(size_t)NN * DD];
__device__ float g_XB[(size_t)NN * DD];
__device__ float g_sums[DD];
__device__ float g_sqs[DD];
__device__ float g_scale[DD];
__device__ float g_shift[DD];

// ---------------- degree + norm ----------------
__global__ void deg_kernel(const int* __restrict__ src, const int* __restrict__ dst,
                           float* __restrict__ deg_out, float* __restrict__ deg_in, int E) {
    int t = blockIdx.x * blockDim.x + threadIdx.x;
    if (t >= E) return;
    atomicAdd(&deg_out[src[t]], 1.0f);
    atomicAdd(&deg_in[dst[t]], 1.0f);
}

__global__ void norm_kernel(float* __restrict__ ns, float* __restrict__ nd, int n) {
    int t = blockIdx.x * blockDim.x + threadIdx.x;
    if (t >= n) return;
    ns[t] = rsqrtf(fmaxf(ns[t], 1.0f));
    nd[t] = rsqrtf(fmaxf(nd[t], 1.0f));
}

// ---------------- SGEMM: C[M,Nn] = (rowscale .* A)[M,K] @ B[K,Nn] + bias ----------------
#define BM 64
#define BN 64
#define BK 16
#define TM 4
#define TN 4
__global__ __launch_bounds__(256) void sgemm_kernel(
    const float* __restrict__ A, const float* __restrict__ B,
    const float* __restrict__ bias, const float* __restrict__ rowscale,
    float* __restrict__ C, int M, int K, int Nn)
{
    __shared__ float As[BK][BM];
    __shared__ float Bs[BK][BN];
    int tid = threadIdx.x;
    int block_row = blockIdx.y * BM;
    int block_col = blockIdx.x * BN;
    int tx = tid & 15;   // 0..15 -> output col group
    int ty = tid >> 4;   // 0..15 -> output row group
    float acc[TM][TN];
#pragma unroll
    for (int i = 0; i < TM; i++)
#pragma unroll
        for (int j = 0; j < TN; j++) acc[i][j] = 0.f;

    for (int k0 = 0; k0 < K; k0 += BK) {
        // load A tile (BM x BK), 4 consecutive K-elems per thread
        {
            int r = tid >> 2;
            int c = (tid & 3) * 4;
            int grow = block_row + r;
            float4 v = make_float4(0.f, 0.f, 0.f, 0.f);
            if (grow < M) {
                v = *(const float4*)&A[(size_t)grow * K + k0 + c];
                if (rowscale) {
                    float s = rowscale[grow];
                    v.x *= s; v.y *= s; v.z *= s; v.w *= s;
                }
            }
            As[c + 0][r] = v.x; As[c + 1][r] = v.y;
            As[c + 2][r] = v.z; As[c + 3][r] = v.w;
        }
        // load B tile (BK x BN)
        {
            int r = tid >> 4;
            int c = (tid & 15) * 4;
            float4 v = *(const float4*)&B[(size_t)(k0 + r) * Nn + block_col + c];
            Bs[r][c + 0] = v.x; Bs[r][c + 1] = v.y;
            Bs[r][c + 2] = v.z; Bs[r][c + 3] = v.w;
        }
        __syncthreads();
#pragma unroll
        for (int kk = 0; kk < BK; kk++) {
            float a[TM], b[TN];
#pragma unroll
            for (int i = 0; i < TM; i++) a[i] = As[kk][ty * TM + i];
#pragma unroll
            for (int j = 0; j < TN; j++) b[j] = Bs[kk][tx * TN + j];
#pragma unroll
            for (int i = 0; i < TM; i++)
#pragma unroll
                for (int j = 0; j < TN; j++) acc[i][j] += a[i] * b[j];
        }
        __syncthreads();
    }
#pragma unroll
    for (int i = 0; i < TM; i++) {
        int grow = block_row + ty * TM + i;
        if (grow >= M) continue;
#pragma unroll
        for (int j = 0; j < TN; j++) {
            int gcol = block_col + tx * TN + j;
            C[(size_t)grow * Nn + gcol] = acc[i][j] + bias[gcol];
        }
    }
}

// ---------------- edge scatter: Out[dst] += X[src] * norm_s[src] ----------------
__global__ void scatter_kernel(const float* __restrict__ X, const int* __restrict__ src,
                               const int* __restrict__ dst, const float* __restrict__ ns,
                               float* __restrict__ Out, int E)
{
    long tid = (long)blockIdx.x * blockDim.x + threadIdx.x;
    if (tid >= (long)E * 64) return;
    int e = (int)(tid >> 6);
    int j = (int)(tid & 63);
    int s = __ldg(&src[e]);
    int d = __ldg(&dst[e]);
    float sc = __ldg(&ns[s]);
    float4 v = *(const float4*)&X[(size_t)s * DD + j * 4];
    float* o = &Out[(size_t)d * DD + j * 4];
    atomicAdd(o + 0, v.x * sc);
    atomicAdd(o + 1, v.y * sc);
    atomicAdd(o + 2, v.z * sc);
    atomicAdd(o + 3, v.w * sc);
}

// ---------------- batchnorm stats (column sums over rows) ----------------
__global__ void bn_stats_kernel(const float* __restrict__ X, float* __restrict__ sums,
                                float* __restrict__ sqs, int Nrows)
{
    int col = threadIdx.x;  // 256 threads, one column each
    int rows_per = (Nrows + gridDim.x - 1) / gridDim.x;
    int r0 = blockIdx.x * rows_per;
    int r1 = min(r0 + rows_per, Nrows);
    float s = 0.f, q = 0.f;
    for (int r = r0; r < r1; r++) {
        float v = X[(size_t)r * DD + col];
        s += v; q += v * v;
    }
    atomicAdd(&sums[col], s);
    atomicAdd(&sqs[col], q);
}

__global__ void bn_finalize_kernel(const float* __restrict__ sums, const float* __restrict__ sqs,
                                   const float* __restrict__ gamma, const float* __restrict__ beta,
                                   float* __restrict__ scale, float* __restrict__ shift, int Nrows)
{
    int c = threadIdx.x;
    float invn = 1.0f / (float)Nrows;
    float mu = sums[c] * invn;
    float var = sqs[c] * invn - mu * mu;
    float inv = rsqrtf(var + 1e-5f);
    float sc = gamma[c] * inv;
    scale[c] = sc;
    shift[c] = beta[c] - mu * sc;
}

__global__ void bn_apply_elu_kernel(float* __restrict__ X, const float* __restrict__ scale,
                                    const float* __restrict__ shift, long total)
{
    long t = (long)blockIdx.x * blockDim.x + threadIdx.x;
    if (t >= total) return;
    int col = (int)(t & (DD - 1));
    float y = X[t] * scale[col] + shift[col];
    X[t] = (y > 0.f) ? y : expm1f(y);
}

// ---------------- classifier head: Out[N,C] = X[N,D] @ W[D,C] + b ----------------
#define HEAD_ROWS 8
__global__ __launch_bounds__(CC * HEAD_ROWS) void logits_kernel(
    const float* __restrict__ X, const float* __restrict__ W,
    const float* __restrict__ b, float* __restrict__ Out, int Nrows)
{
    __shared__ float Ws[DD * CC];  // 40 KB
    for (int i = threadIdx.x; i < DD * CC; i += blockDim.x) Ws[i] = W[i];
    __syncthreads();
    int c = threadIdx.x % CC;
    int rloc = threadIdx.x / CC;
    int row = blockIdx.x * HEAD_ROWS + rloc;
    if (row >= Nrows) return;
    const float* a = &X[(size_t)row * DD];
    float acc = b[c];
#pragma unroll 8
    for (int k = 0; k < DD; k += 4) {
        float4 av = *(const float4*)&a[k];
        acc += av.x * Ws[(k + 0) * CC + c];
        acc += av.y * Ws[(k + 1) * CC + c];
        acc += av.z * Ws[(k + 2) * CC + c];
        acc += av.w * Ws[(k + 3) * CC + c];
    }
    Out[(size_t)row * CC + c] = acc;
}

// ---------------- driver ----------------
extern "C" void kernel_launch(void* const* d_in, const int* in_sizes, int n_in,
                              void* d_out, int out_size)
{
    const float* feat  = (const float*)d_in[0];
    const int*   src   = (const int*)d_in[1];
    const int*   dst   = (const int*)d_in[2];
    const float* W_fc  = (const float*)d_in[3];
    const float* b_fc  = (const float*)d_in[4];
    const float* W1    = (const float*)d_in[5];
    const float* b1    = (const float*)d_in[6];
    const float* W2    = (const float*)d_in[7];
    const float* b2    = (const float*)d_in[8];
    const float* W3    = (const float*)d_in[9];
    const float* b3    = (const float*)d_in[10];
    const float* gamma = (const float*)d_in[11];
    const float* beta  = (const float*)d_in[12];
    const float* W_lin = (const float*)d_in[13];
    const float* b_lin = (const float*)d_in[14];

    const int D = in_sizes[4];             // 256
    const int F = in_sizes[3] / D;         // 1024
    const int N = in_sizes[0] / F;         // 50000
    const int E = in_sizes[1];             // 300000

    float *p_norms, *p_normd, *p_XA, *p_XB, *p_sums, *p_sqs, *p_scale, *p_shift;
    cudaGetSymbolAddress((void**)&p_norms, g_norms);
    cudaGetSymbolAddress((void**)&p_normd, g_normd);
    cudaGetSymbolAddress((void**)&p_XA, g_XA);
    cudaGetSymbolAddress((void**)&p_XB, g_XB);
    cudaGetSymbolAddress((void**)&p_sums, g_sums);
    cudaGetSymbolAddress((void**)&p_sqs, g_sqs);
    cudaGetSymbolAddress((void**)&p_scale, g_scale);
    cudaGetSymbolAddress((void**)&p_shift, g_shift);

    float* out_x = (float*)d_out;                       // [N, D]
    float* out_logits = (float*)d_out + (size_t)N * D;  // [N, C]

    // 1. degrees -> norms
    cudaMemsetAsync(p_norms, 0, N * sizeof(float));
    cudaMemsetAsync(p_normd, 0, N * sizeof(float));
    deg_kernel<<<(E + 255) / 256, 256>>>(src, dst, p_norms, p_normd, E);
    norm_kernel<<<(N + 255) / 256, 256>>>(p_norms, p_normd, N);

    // 2. x = feat @ W_fc + b_fc   -> XA
    {
        dim3 grid(D / BN, (N + BM - 1) / BM);
        sgemm_kernel<<<grid, 256>>>(feat, W_fc, b_fc, nullptr, p_XA, N, F, D);
    }

    const float* Ws[3] = {W1, W2, W3};
    const float* bs[3] = {b1, b2, b3};
    long scat_threads = (long)E * 64;
    int scat_blocks = (int)((scat_threads + 255) / 256);
    long total = (long)N * D;

    for (int l = 0; l < 3; l++) {
        // scatter: XB[dst] += XA[src] * norm_s[src]
        cudaMemsetAsync(p_XB, 0, (size_t)N * D * sizeof(float));
        scatter_kernel<<<scat_blocks, 256>>>(p_XA, src, dst, p_norms, p_XB, E);
        // gemm: dest = (XB * norm_d) @ W + b
        float* dest = (l < 2) ? p_XA : out_x;
        dim3 grid(D / BN, (N + BM - 1) / BM);
        sgemm_kernel<<<grid, 256>>>(p_XB, Ws[l], bs[l], p_normd, dest, N, D, D);
        if (l < 2) {
            cudaMemsetAsync(p_sums, 0, D * sizeof(float));
            cudaMemsetAsync(p_sqs, 0, D * sizeof(float));
            bn_stats_kernel<<<512, D>>>(p_XA, p_sums, p_sqs, N);
            bn_finalize_kernel<<<1, D>>>(p_sums, p_sqs, gamma, beta, p_scale, p_shift, N);
            bn_apply_elu_kernel<<<(int)((total + 255) / 256), 256>>>(p_XA, p_scale, p_shift, total);
        }
    }

    // 3. logits = x @ W_lin + b_lin
    logits_kernel<<<(N + HEAD_ROWS - 1) / HEAD_ROWS, CC * HEAD_ROWS>>>(
        out_x, W_lin, b_lin, out_logits, N);
}

// round 2
// speedup vs baseline: 1.3119x; 1.3119x over previous
#include <cuda_runtime.h>
#include <cuda_bf16.h>
#include <math.h>
#include <stdint.h>

#define NN 50000
#define EE 300000
#define DD 256
#define FF 1024
#define CC 40

// ---------------- scratch (device globals) ----------------
__device__ float g_norms[NN];
__device__ float g_normd[NN];
__device__ int   g_odeg[NN];
__device__ int   g_ideg[NN];
__device__ int   g_offs[NN + 1];
__device__ int   g_cursor[NN];
__device__ int   g_esrc[EE];
__device__ float g_XA[(size_t)NN * DD];
__device__ float g_XB[(size_t)NN * DD];
__device__ float g_sums[DD];
__device__ float g_sqs[DD];
__device__ float g_scale[DD];
__device__ float g_shift[DD];

// ---------------- degree + norm ----------------
__global__ void deg_kernel(const int* __restrict__ src, const int* __restrict__ dst,
                           int* __restrict__ od, int* __restrict__ id, int E) {
    int t = blockIdx.x * blockDim.x + threadIdx.x;
    if (t >= E) return;
    atomicAdd(&od[src[t]], 1);
    atomicAdd(&id[dst[t]], 1);
}

__global__ void norm_kernel(const int* __restrict__ od, const int* __restrict__ id,
                            float* __restrict__ ns, float* __restrict__ nd, int n) {
    int t = blockIdx.x * blockDim.x + threadIdx.x;
    if (t >= n) return;
    ns[t] = rsqrtf(fmaxf((float)od[t], 1.0f));
    nd[t] = rsqrtf(fmaxf((float)id[t], 1.0f));
}

// ---------------- CSR build ----------------
#define SCAN_T 1024
__global__ void scan_kernel(const int* __restrict__ deg, int* __restrict__ offs,
                            int* __restrict__ cursor, int n) {
    __shared__ int sh[SCAN_T];
    int t = threadIdx.x;
    int chunk = (n + SCAN_T - 1) / SCAN_T;
    int a = t * chunk, b = min(a + chunk, n);
    int s = 0;
    for (int i = a; i < b; i++) s += deg[i];
    sh[t] = s;
    __syncthreads();
    for (int off = 1; off < SCAN_T; off <<= 1) {
        int v = (t >= off) ? sh[t - off] : 0;
        __syncthreads();
        sh[t] += v;
        __syncthreads();
    }
    int run = sh[t] - s;  // exclusive prefix
    for (int i = a; i < b; i++) {
        offs[i] = run;
        cursor[i] = run;
        run += deg[i];
    }
    if (t == SCAN_T - 1) offs[n] = run;
}

__global__ void fill_kernel(const int* __restrict__ src, const int* __restrict__ dst,
                            int* __restrict__ cursor, int* __restrict__ esrc, int E) {
    int e = blockIdx.x * blockDim.x + threadIdx.x;
    if (e >= E) return;
    int p = atomicAdd(&cursor[dst[e]], 1);
    esrc[p] = src[e];
}

// ---------------- SpMM gather: Out[r] = sum_{e: dst=r} X[src_e] * ns[src_e] ----------------
__global__ __launch_bounds__(256) void spmm_gather(
    const float* __restrict__ X, const int* __restrict__ esrc,
    const int* __restrict__ offs, const float* __restrict__ ns,
    float* __restrict__ Out, int n)
{
    int row = blockIdx.x * 4 + (threadIdx.x >> 6);
    int lane = threadIdx.x & 63;
    if (row >= n) return;
    int o0 = offs[row], o1 = offs[row + 1];
    float4 acc = make_float4(0.f, 0.f, 0.f, 0.f);
    for (int i = o0; i < o1; i++) {
        int s = __ldg(&esrc[i]);
        float sc = __ldg(&ns[s]);
        float4 v = *(const float4*)&X[(size_t)s * DD + lane * 4];
        acc.x += v.x * sc; acc.y += v.y * sc;
        acc.z += v.z * sc; acc.w += v.w * sc;
    }
    *(float4*)&Out[(size_t)row * DD + lane * 4] = acc;
}

// ---------------- TF32 tensor-core GEMM ----------------
// C[M,Nn] = (rowscale .* A)[M,K] @ B[K,Nn] + bias
#define GBM 128
#define GBN 128
#define GBK 32

__device__ __forceinline__ uint32_t f2tf(float f) {
    uint32_t u;
    asm("cvt.rna.tf32.f32 %0, %1;" : "=r"(u) : "f"(f));
    return u;
}

__device__ __forceinline__ void mma8(float* c,
    uint32_t a0, uint32_t a1, uint32_t a2, uint32_t a3,
    uint32_t b0, uint32_t b1)
{
    asm volatile(
        "mma.sync.aligned.m16n8k8.row.col.f32.tf32.tf32.f32 "
        "{%0,%1,%2,%3}, {%4,%5,%6,%7}, {%8,%9}, {%0,%1,%2,%3};"
        : "+f"(c[0]), "+f"(c[1]), "+f"(c[2]), "+f"(c[3])
        : "r"(a0), "r"(a1), "r"(a2), "r"(a3), "r"(b0), "r"(b1));
}

__global__ __launch_bounds__(256) void mma_gemm(
    const float* __restrict__ A, const float* __restrict__ B,
    const float* __restrict__ bias, const float* __restrict__ rowscale,
    float* __restrict__ C, int M, int K, int Nn)
{
    __shared__ uint32_t As[GBM][GBK + 1];
    __shared__ uint32_t Bs[GBN][GBK + 1];
    const int tid = threadIdx.x;
    const int lane = tid & 31;
    const int warp = tid >> 5;
    const int wm = warp & 1;    // 0..1  (64 rows each)
    const int wn = warp >> 1;   // 0..3  (32 cols each)
    const int brow = blockIdx.y * GBM;
    const int bcol = blockIdx.x * GBN;

    float acc[4][4][4];
#pragma unroll
    for (int i = 0; i < 4; i++)
#pragma unroll
        for (int j = 0; j < 4; j++)
#pragma unroll
            for (int l = 0; l < 4; l++) acc[i][j][l] = 0.f;

    int aR[4], aK[4], bK[4], bN[4];
#pragma unroll
    for (int i = 0; i < 4; i++) {
        int idx = tid + i * 256;
        aR[i] = idx >> 3;       // 0..127
        aK[i] = (idx & 7) * 4;  // 0..28
        bK[i] = idx >> 5;       // 0..31
        bN[i] = (idx & 31) * 4; // 0..124
    }

    float4 ra[4], rb[4];
    // prologue load (k0 = 0)
#pragma unroll
    for (int i = 0; i < 4; i++) {
        int gr = brow + aR[i];
        if (gr < M) {
            ra[i] = *(const float4*)&A[(size_t)gr * K + aK[i]];
            if (rowscale) {
                float s = __ldg(&rowscale[gr]);
                ra[i].x *= s; ra[i].y *= s; ra[i].z *= s; ra[i].w *= s;
            }
        } else ra[i] = make_float4(0.f, 0.f, 0.f, 0.f);
        rb[i] = *(const float4*)&B[(size_t)bK[i] * Nn + bcol + bN[i]];
    }

    const int KT = K / GBK;
    for (int kt = 0; kt < KT; kt++) {
        // store staged tile to shared (tf32-converted, xor-swizzled)
#pragma unroll
        for (int i = 0; i < 4; i++) {
            int r = aR[i], k = aK[i];
            int sw = (r & 3) << 3;
            As[r][(k + 0) ^ sw] = f2tf(ra[i].x);
            As[r][(k + 1) ^ sw] = f2tf(ra[i].y);
            As[r][(k + 2) ^ sw] = f2tf(ra[i].z);
            As[r][(k + 3) ^ sw] = f2tf(ra[i].w);
            int kk = bK[i], n = bN[i];
            Bs[n + 0][kk ^ (0 << 3)] = f2tf(rb[i].x);
            Bs[n + 1][kk ^ (1 << 3)] = f2tf(rb[i].y);
            Bs[n + 2][kk ^ (2 << 3)] = f2tf(rb[i].z);
            Bs[n + 3][kk ^ (3 << 3)] = f2tf(rb[i].w);
        }
        __syncthreads();

        if (kt + 1 < KT) {
            int k0 = (kt + 1) * GBK;
#pragma unroll
            for (int i = 0; i < 4; i++) {
                int gr = brow + aR[i];
                if (gr < M) {
                    ra[i] = *(const float4*)&A[(size_t)gr * K + k0 + aK[i]];
                    if (rowscale) {
                        float s = __ldg(&rowscale[gr]);
                        ra[i].x *= s; ra[i].y *= s; ra[i].z *= s; ra[i].w *= s;
                    }
                } else ra[i] = make_float4(0.f, 0.f, 0.f, 0.f);
                rb[i] = *(const float4*)&B[(size_t)(k0 + bK[i]) * Nn + bcol + bN[i]];
            }
        }

#pragma unroll
        for (int kk = 0; kk < 4; kk++) {
            uint32_t af[4][4], bf[4][2];
            const int kc = kk * 8 + (lane & 3);
#pragma unroll
            for (int mi = 0; mi < 4; mi++) {
                int rr = wm * 64 + mi * 16 + (lane >> 2);
                int sw = (rr & 3) << 3;
                af[mi][0] = As[rr][kc ^ sw];
                af[mi][1] = As[rr + 8][kc ^ sw];
                af[mi][2] = As[rr][(kc + 4) ^ sw];
                af[mi][3] = As[rr + 8][(kc + 4) ^ sw];
            }
#pragma unroll
            for (int ni = 0; ni < 4; ni++) {
                int nn = wn * 32 + ni * 8 + (lane >> 2);
                int sw = (nn & 3) << 3;
                bf[ni][0] = Bs[nn][kc ^ sw];
                bf[ni][1] = Bs[nn][(kc + 4) ^ sw];
            }
#pragma unroll
            for (int mi = 0; mi < 4; mi++)
#pragma unroll
                for (int ni = 0; ni < 4; ni++)
                    mma8(acc[mi][ni], af[mi][0], af[mi][1], af[mi][2], af[mi][3],
                         bf[ni][0], bf[ni][1]);
        }
        __syncthreads();
    }

    // epilogue
#pragma unroll
    for (int mi = 0; mi < 4; mi++) {
        int r0 = brow + wm * 64 + mi * 16 + (lane >> 2);
#pragma unroll
        for (int ni = 0; ni < 4; ni++) {
            int c = bcol + wn * 32 + ni * 8 + (lane & 3) * 2;
            float b0 = bias[c], b1 = bias[c + 1];
            if (r0 < M) {
                float2 o = make_float2(acc[mi][ni][0] + b0, acc[mi][ni][1] + b1);
                *(float2*)&C[(size_t)r0 * Nn + c] = o;
            }
            if (r0 + 8 < M) {
                float2 o = make_float2(acc[mi][ni][2] + b0, acc[mi][ni][3] + b1);
                *(float2*)&C[(size_t)(r0 + 8) * Nn + c] = o;
            }
        }
    }
}

// ---------------- batchnorm ----------------
__global__ void bn_stats_kernel(const float* __restrict__ X, float* __restrict__ sums,
                                float* __restrict__ sqs, int Nrows)
{
    int col = threadIdx.x;
    int rows_per = (Nrows + gridDim.x - 1) / gridDim.x;
    int r0 = blockIdx.x * rows_per;
    int r1 = min(r0 + rows_per, Nrows);
    float s = 0.f, q = 0.f;
    for (int r = r0; r < r1; r++) {
        float v = X[(size_t)r * DD + col];
        s += v; q += v * v;
    }
    atomicAdd(&sums[col], s);
    atomicAdd(&sqs[col], q);
}

__global__ void bn_finalize_kernel(const float* __restrict__ sums, const float* __restrict__ sqs,
                                   const float* __restrict__ gamma, const float* __restrict__ beta,
                                   float* __restrict__ scale, float* __restrict__ shift, int Nrows)
{
    int c = threadIdx.x;
    float invn = 1.0f / (float)Nrows;
    float mu = sums[c] * invn;
    float var = sqs[c] * invn - mu * mu;
    float inv = rsqrtf(var + 1e-5f);
    float sc = gamma[c] * inv;
    scale[c] = sc;
    shift[c] = beta[c] - mu * sc;
}

__global__ void bn_apply_elu_kernel(float* __restrict__ X, const float* __restrict__ scale,
                                    const float* __restrict__ shift, long total)
{
    long t = (long)blockIdx.x * blockDim.x + threadIdx.x;
    if (t >= total) return;
    int col = (int)(t & (DD - 1));
    float y = X[t] * scale[col] + shift[col];
    X[t] = (y > 0.f) ? y : expm1f(y);
}

// ---------------- classifier head ----------------
#define HEAD_ROWS 8
__global__ __launch_bounds__(CC * HEAD_ROWS) void logits_kernel(
    const float* __restrict__ X, const float* __restrict__ W,
    const float* __restrict__ b, float* __restrict__ Out, int Nrows)
{
    __shared__ float Ws[DD * CC];
    for (int i = threadIdx.x; i < DD * CC; i += blockDim.x) Ws[i] = W[i];
    __syncthreads();
    int c = threadIdx.x % CC;
    int rloc = threadIdx.x / CC;
    int row = blockIdx.x * HEAD_ROWS + rloc;
    if (row >= Nrows) return;
    const float* a = &X[(size_t)row * DD];
    float acc = b[c];
#pragma unroll 8
    for (int k = 0; k < DD; k += 4) {
        float4 av = *(const float4*)&a[k];
        acc += av.x * Ws[(k + 0) * CC + c];
        acc += av.y * Ws[(k + 1) * CC + c];
        acc += av.z * Ws[(k + 2) * CC + c];
        acc += av.w * Ws[(k + 3) * CC + c];
    }
    Out[(size_t)row * CC + c] = acc;
}

// ---------------- driver ----------------
extern "C" void kernel_launch(void* const* d_in, const int* in_sizes, int n_in,
                              void* d_out, int out_size)
{
    const float* feat  = (const float*)d_in[0];
    const int*   src   = (const int*)d_in[1];
    const int*   dst   = (const int*)d_in[2];
    const float* W_fc  = (const float*)d_in[3];
    const float* b_fc  = (const float*)d_in[4];
    const float* W1    = (const float*)d_in[5];
    const float* b1    = (const float*)d_in[6];
    const float* W2    = (const float*)d_in[7];
    const float* b2    = (const float*)d_in[8];
    const float* W3    = (const float*)d_in[9];
    const float* b3    = (const float*)d_in[10];
    const float* gamma = (const float*)d_in[11];
    const float* beta  = (const float*)d_in[12];
    const float* W_lin = (const float*)d_in[13];
    const float* b_lin = (const float*)d_in[14];

    const int D = in_sizes[4];             // 256
    const int F = in_sizes[3] / D;         // 1024
    const int N = in_sizes[0] / F;         // 50000
    const int E = in_sizes[1];             // 300000

    float *p_norms, *p_normd, *p_XA, *p_XB, *p_sums, *p_sqs, *p_scale, *p_shift;
    int *p_odeg, *p_ideg, *p_offs, *p_cursor, *p_esrc;
    cudaGetSymbolAddress((void**)&p_norms, g_norms);
    cudaGetSymbolAddress((void**)&p_normd, g_normd);
    cudaGetSymbolAddress((void**)&p_odeg, g_odeg);
    cudaGetSymbolAddress((void**)&p_ideg, g_ideg);
    cudaGetSymbolAddress((void**)&p_offs, g_offs);
    cudaGetSymbolAddress((void**)&p_cursor, g_cursor);
    cudaGetSymbolAddress((void**)&p_esrc, g_esrc);
    cudaGetSymbolAddress((void**)&p_XA, g_XA);
    cudaGetSymbolAddress((void**)&p_XB, g_XB);
    cudaGetSymbolAddress((void**)&p_sums, g_sums);
    cudaGetSymbolAddress((void**)&p_sqs, g_sqs);
    cudaGetSymbolAddress((void**)&p_scale, g_scale);
    cudaGetSymbolAddress((void**)&p_shift, g_shift);

    float* out_x = (float*)d_out;                       // [N, D]
    float* out_logits = (float*)d_out + (size_t)N * D;  // [N, C]

    // 1. degrees -> norms + CSR
    cudaMemsetAsync(p_odeg, 0, N * sizeof(int));
    cudaMemsetAsync(p_ideg, 0, N * sizeof(int));
    deg_kernel<<<(E + 255) / 256, 256>>>(src, dst, p_odeg, p_ideg, E);
    norm_kernel<<<(N + 255) / 256, 256>>>(p_odeg, p_ideg, p_norms, p_normd, N);
    scan_kernel<<<1, SCAN_T>>>(p_ideg, p_offs, p_cursor, N);
    fill_kernel<<<(E + 255) / 256, 256>>>(src, dst, p_cursor, p_esrc, E);

    // 2. x = feat @ W_fc + b_fc -> XA
    {
        dim3 grid(D / GBN, (N + GBM - 1) / GBM);
        mma_gemm<<<grid, 256>>>(feat, W_fc, b_fc, nullptr, p_XA, N, F, D);
    }

    const float* Ws[3] = {W1, W2, W3};
    const float* bs[3] = {b1, b2, b3};
    long total = (long)N * D;

    for (int l = 0; l < 3; l++) {
        spmm_gather<<<(N + 3) / 4, 256>>>(p_XA, p_esrc, p_offs, p_norms, p_XB, N);
        float* dest = (l < 2) ? p_XA : out_x;
        dim3 grid(D / GBN, (N + GBM - 1) / GBM);
        mma_gemm<<<grid, 256>>>(p_XB, Ws[l], bs[l], p_normd, dest, N, D, D);
        if (l < 2) {
            cudaMemsetAsync(p_sums, 0, D * sizeof(float));
            cudaMemsetAsync(p_sqs, 0, D * sizeof(float));
            bn_stats_kernel<<<512, D>>>(p_XA, p_sums, p_sqs, N);
            bn_finalize_kernel<<<1, D>>>(p_sums, p_sqs, gamma, beta, p_scale, p_shift, N);
            bn_apply_elu_kernel<<<(int)((total + 255) / 256), 256>>>(p_XA, p_scale, p_shift, total);
        }
    }

    // 3. logits
    logits_kernel<<<(N + HEAD_ROWS - 1) / HEAD_ROWS, CC * HEAD_ROWS>>>(
        out_x, W_lin, b_lin, out_logits, N);
}

// round 4
// speedup vs baseline: 2.1026x; 1.6027x over previous
#include <cuda_runtime.h>
#include <cuda_fp16.h>
#include <math.h>
#include <stdint.h>

#define NN 50000
#define EE 300000
#define DD 256
#define FF 1024
#define CC 40

// ---------------- scratch (device globals) ----------------
__device__ float g_norms[NN];
__device__ float g_normd[NN];
__device__ int   g_odeg[NN];
__device__ int   g_ideg[NN];
__device__ int   g_offs[NN + 1];
__device__ int   g_cursor[NN];
__device__ int   g_esrc[EE];
__device__ float g_XA[(size_t)NN * DD];
__device__ float g_XB[(size_t)NN * DD];
__device__ float g_sums[DD];
__device__ float g_sqs[DD];
__device__ float g_scale[DD];
__device__ float g_shift[DD];
// transposed weights: WT_fc [256][1024], WT1/2/3 [256][256]
__device__ float g_WT[(size_t)DD * FF + 3 * (size_t)DD * DD];

// ---------------- helpers ----------------
__device__ __forceinline__ uint32_t smem_u32(const void* p) {
    uint32_t a;
    asm("{ .reg .u64 t; cvta.to.shared.u64 t, %1; cvt.u32.u64 %0, t; }" : "=r"(a) : "l"(p));
    return a;
}
__device__ __forceinline__ uint32_t f22h(float a, float b) {
    __half2 h = __float22half2_rn(make_float2(a, b));
    return *(uint32_t*)&h;
}
__device__ __forceinline__ void ldsm4(uint32_t* r, uint32_t addr) {
    asm volatile("ldmatrix.sync.aligned.m8n8.x4.shared.b16 {%0,%1,%2,%3}, [%4];"
                 : "=r"(r[0]), "=r"(r[1]), "=r"(r[2]), "=r"(r[3]) : "r"(addr));
}
__device__ __forceinline__ void mma16816(float* c, const uint32_t* a, const uint32_t* b) {
    asm volatile(
        "mma.sync.aligned.m16n8k16.row.col.f32.f16.f16.f32 "
        "{%0,%1,%2,%3}, {%4,%5,%6,%7}, {%8,%9}, {%0,%1,%2,%3};"
        : "+f"(c[0]), "+f"(c[1]), "+f"(c[2]), "+f"(c[3])
        : "r"(a[0]), "r"(a[1]), "r"(a[2]), "r"(a[3]), "r"(b[0]), "r"(b[1]));
}

// swizzled half offset within a [rows][32] half tile (64B rows, 4x16B groups)
__device__ __forceinline__ int swoff(int r, int c) {
    return r * 32 + ((((c >> 3) ^ ((r >> 1) & 3)) << 3)) + (c & 7);
}

// ---------------- degree + norm ----------------
__global__ void deg_kernel(const int* __restrict__ src, const int* __restrict__ dst,
                           int* __restrict__ od, int* __restrict__ id, int E) {
    int t = blockIdx.x * blockDim.x + threadIdx.x;
    if (t >= E) return;
    atomicAdd(&od[src[t]], 1);
    atomicAdd(&id[dst[t]], 1);
}

__global__ void norm_kernel(const int* __restrict__ od, const int* __restrict__ id,
                            float* __restrict__ ns, float* __restrict__ nd, int n) {
    int t = blockIdx.x * blockDim.x + threadIdx.x;
    if (t >= n) return;
    ns[t] = rsqrtf(fmaxf((float)od[t], 1.0f));
    nd[t] = rsqrtf(fmaxf((float)id[t], 1.0f));
}

// ---------------- CSR build ----------------
#define SCAN_T 1024
__global__ void scan_kernel(const int* __restrict__ deg, int* __restrict__ offs,
                            int* __restrict__ cursor, int n) {
    __shared__ int sh[SCAN_T];
    int t = threadIdx.x;
    int chunk = (n + SCAN_T - 1) / SCAN_T;
    int a = t * chunk, b = min(a + chunk, n);
    int s = 0;
    for (int i = a; i < b; i++) s += deg[i];
    sh[t] = s;
    __syncthreads();
    for (int off = 1; off < SCAN_T; off <<= 1) {
        int v = (t >= off) ? sh[t - off] : 0;
        __syncthreads();
        sh[t] += v;
        __syncthreads();
    }
    int run = sh[t] - s;
    for (int i = a; i < b; i++) {
        offs[i] = run;
        cursor[i] = run;
        run += deg[i];
    }
    if (t == SCAN_T - 1) offs[n] = run;
}

__global__ void fill_kernel(const int* __restrict__ src, const int* __restrict__ dst,
                            int* __restrict__ cursor, int* __restrict__ esrc, int E) {
    int e = blockIdx.x * blockDim.x + threadIdx.x;
    if (e >= E) return;
    int p = atomicAdd(&cursor[dst[e]], 1);
    esrc[p] = src[e];
}

// ---------------- SpMM gather ----------------
__global__ __launch_bounds__(256) void spmm_gather(
    const float* __restrict__ X, const int* __restrict__ esrc,
    const int* __restrict__ offs, const float* __restrict__ ns,
    float* __restrict__ Out, int n)
{
    int row = blockIdx.x * 4 + (threadIdx.x >> 6);
    int lane = threadIdx.x & 63;
    if (row >= n) return;
    int o0 = offs[row], o1 = offs[row + 1];
    float4 acc = make_float4(0.f, 0.f, 0.f, 0.f);
    int i = o0;
    for (; i + 1 < o1; i += 2) {
        int s0 = __ldg(&esrc[i]), s1 = __ldg(&esrc[i + 1]);
        float c0 = __ldg(&ns[s0]), c1 = __ldg(&ns[s1]);
        float4 v0 = *(const float4*)&X[(size_t)s0 * DD + lane * 4];
        float4 v1 = *(const float4*)&X[(size_t)s1 * DD + lane * 4];
        acc.x += v0.x * c0 + v1.x * c1;
        acc.y += v0.y * c0 + v1.y * c1;
        acc.z += v0.z * c0 + v1.z * c1;
        acc.w += v0.w * c0 + v1.w * c1;
    }
    if (i < o1) {
        int s = __ldg(&esrc[i]);
        float c = __ldg(&ns[s]);
        float4 v = *(const float4*)&X[(size_t)s * DD + lane * 4];
        acc.x += v.x * c; acc.y += v.y * c;
        acc.z += v.z * c; acc.w += v.w * c;
    }
    *(float4*)&Out[(size_t)row * DD + lane * 4] = acc;
}

// ---------------- weight transpose ----------------
__global__ void transpose_kernel(const float* __restrict__ W, float* __restrict__ Wt,
                                 int K, int Nn) {
    __shared__ float t[32][33];
    int bx = blockIdx.x * 32;  // K
    int by = blockIdx.y * 32;  // N
    int x = threadIdx.x, y = threadIdx.y;
    for (int j = 0; j < 32; j += 8)
        t[y + j][x] = W[(size_t)(bx + y + j) * Nn + by + x];
    __syncthreads();
    for (int j = 0; j < 32; j += 8)
        Wt[(size_t)(by + y + j) * K + bx + x] = t[x][y + j];
}

// ---------------- fp16 mma GEMM: C[M,256] = (rowscale.*A)[M,K] @ W + bias ----------------
// Bt = W^T, [256][K] row-major. Block 128x128, 256 threads, 8 warps (warp tile 64x32).
__global__ __launch_bounds__(256, 2) void mma_gemm(
    const float* __restrict__ A, const float* __restrict__ Bt,
    const float* __restrict__ bias, const float* __restrict__ rowscale,
    float* __restrict__ C, int M, int K, int Nn)
{
    __shared__ __align__(16) __half As[2][128 * 32];
    __shared__ __align__(16) __half Bs[2][128 * 32];

    const int tid = threadIdx.x;
    const int lane = tid & 31;
    const int warp = tid >> 5;
    const int wm = warp & 1;    // 64 rows
    const int wn = warp >> 1;   // 32 cols
    const int brow = blockIdx.y * 128;
    const int bcol = blockIdx.x * 128;
    const int l8 = lane & 7;
    const int q = lane >> 3;

    float acc[4][4][4];
#pragma unroll
    for (int i = 0; i < 4; i++)
#pragma unroll
        for (int j = 0; j < 4; j++)
#pragma unroll
            for (int l = 0; l < 4; l++) acc[i][j][l] = 0.f;

    // per-thread global load mapping: 4 float4s each for A and B tiles
    int ldR[4], ldC[4];
#pragma unroll
    for (int i = 0; i < 4; i++) {
        int idx = tid + i * 256;
        ldR[i] = idx >> 3;          // 0..127
        ldC[i] = (idx & 7) << 2;    // 0,4,...,28
    }

    float4 ra[4], rb[4];
    const int nch = K >> 5;

    // prologue: load chunk 0
#pragma unroll
    for (int i = 0; i < 4; i++) {
        int gr = brow + ldR[i];
        float4 v = make_float4(0.f, 0.f, 0.f, 0.f);
        if (gr < M) {
            v = *(const float4*)&A[(size_t)gr * K + ldC[i]];
            if (rowscale) {
                float s = __ldg(&rowscale[gr]);
                v.x *= s; v.y *= s; v.z *= s; v.w *= s;
            }
        }
        ra[i] = v;
        rb[i] = *(const float4*)&Bt[(size_t)(bcol + ldR[i]) * K + ldC[i]];
    }
#pragma unroll
    for (int i = 0; i < 4; i++) {
        int o = swoff(ldR[i], ldC[i]);
        *(uint2*)&As[0][o] = make_uint2(f22h(ra[i].x, ra[i].y), f22h(ra[i].z, ra[i].w));
        *(uint2*)&Bs[0][o] = make_uint2(f22h(rb[i].x, rb[i].y), f22h(rb[i].z, rb[i].w));
    }
    __syncthreads();

    for (int c = 0; c < nch; c++) {
        const int buf = c & 1;
        if (c + 1 < nch) {
            int k0 = (c + 1) << 5;
#pragma unroll
            for (int i = 0; i < 4; i++) {
                int gr = brow + ldR[i];
                float4 v = make_float4(0.f, 0.f, 0.f, 0.f);
                if (gr < M) {
                    v = *(const float4*)&A[(size_t)gr * K + k0 + ldC[i]];
                    if (rowscale) {
                        float s = __ldg(&rowscale[gr]);
                        v.x *= s; v.y *= s; v.z *= s; v.w *= s;
                    }
                }
                ra[i] = v;
                rb[i] = *(const float4*)&Bt[(size_t)(bcol + ldR[i]) * K + k0 + ldC[i]];
            }
        }

        // mma over smem[buf]: two k16 halves
#pragma unroll
        for (int kk = 0; kk < 2; kk++) {
            uint32_t af[4][4], bf[4][2];
#pragma unroll
            for (int mi = 0; mi < 4; mi++) {
                int row = wm * 64 + mi * 16 + ((q & 1) << 3) + l8;
                int col = kk * 16 + ((q >> 1) << 3);
                ldsm4(af[mi], smem_u32(&As[buf][swoff(row, col)]));
            }
#pragma unroll
            for (int p = 0; p < 2; p++) {
                int row = wn * 32 + p * 16 + ((q >> 1) << 3) + l8;
                int col = kk * 16 + ((q & 1) << 3);
                uint32_t r4[4];
                ldsm4(r4, smem_u32(&Bs[buf][swoff(row, col)]));
                bf[2 * p][0] = r4[0]; bf[2 * p][1] = r4[1];
                bf[2 * p + 1][0] = r4[2]; bf[2 * p + 1][1] = r4[3];
            }
#pragma unroll
            for (int mi = 0; mi < 4; mi++)
#pragma unroll
                for (int ni = 0; ni < 4; ni++)
                    mma16816(acc[mi][ni], af[mi], bf[ni]);
        }

        if (c + 1 < nch) {
            const int nb = buf ^ 1;
#pragma unroll
            for (int i = 0; i < 4; i++) {
                int o = swoff(ldR[i], ldC[i]);
                *(uint2*)&As[nb][o] = make_uint2(f22h(ra[i].x, ra[i].y), f22h(ra[i].z, ra[i].w));
                *(uint2*)&Bs[nb][o] = make_uint2(f22h(rb[i].x, rb[i].y), f22h(rb[i].z, rb[i].w));
            }
        }
        __syncthreads();
    }

    // epilogue
#pragma unroll
    for (int mi = 0; mi < 4; mi++) {
        int r0 = brow + wm * 64 + mi * 16 + (lane >> 2);
#pragma unroll
        for (int ni = 0; ni < 4; ni++) {
            int cc = bcol + wn * 32 + ni * 8 + (lane & 3) * 2;
            float b0 = bias[cc], b1 = bias[cc + 1];
            if (r0 < M) {
                float2 o = make_float2(acc[mi][ni][0] + b0, acc[mi][ni][1] + b1);
                *(float2*)&C[(size_t)r0 * Nn + cc] = o;
            }
            if (r0 + 8 < M) {
                float2 o = make_float2(acc[mi][ni][2] + b0, acc[mi][ni][3] + b1);
                *(float2*)&C[(size_t)(r0 + 8) * Nn + cc] = o;
            }
        }
    }
}

// ---------------- batchnorm ----------------
__global__ void bn_stats_kernel(const float* __restrict__ X, float* __restrict__ sums,
                                float* __restrict__ sqs, int Nrows)
{
    int col = threadIdx.x;
    int rows_per = (Nrows + gridDim.x - 1) / gridDim.x;
    int r0 = blockIdx.x * rows_per;
    int r1 = min(r0 + rows_per, Nrows);
    float s = 0.f, qv = 0.f;
    for (int r = r0; r < r1; r++) {
        float v = X[(size_t)r * DD + col];
        s += v; qv += v * v;
    }
    atomicAdd(&sums[col], s);
    atomicAdd(&sqs[col], qv);
}

__global__ void bn_finalize_kernel(const float* __restrict__ sums, const float* __restrict__ sqs,
                                   const float* __restrict__ gamma, const float* __restrict__ beta,
                                   float* __restrict__ scale, float* __restrict__ shift, int Nrows)
{
    int c = threadIdx.x;
    float invn = 1.0f / (float)Nrows;
    float mu = sums[c] * invn;
    float var = sqs[c] * invn - mu * mu;
    float inv = rsqrtf(var + 1e-5f);
    float sc = gamma[c] * inv;
    scale[c] = sc;
    shift[c] = beta[c] - mu * sc;
}

__global__ void bn_apply_elu_kernel(float* __restrict__ X, const float* __restrict__ scale,
                                    const float* __restrict__ shift, long total)
{
    long t = (long)blockIdx.x * blockDim.x + threadIdx.x;
    if (t >= total) return;
    int col = (int)(t & (DD - 1));
    float y = X[t] * scale[col] + shift[col];
    X[t] = (y > 0.f) ? y : expm1f(y);
}

// ---------------- classifier head ----------------
#define HEAD_ROWS 8
__global__ __launch_bounds__(CC * HEAD_ROWS) void logits_kernel(
    const float* __restrict__ X, const float* __restrict__ W,
    const float* __restrict__ b, float* __restrict__ Out, int Nrows)
{
    __shared__ float Ws[DD * CC];
    for (int i = threadIdx.x; i < DD * CC; i += blockDim.x) Ws[i] = W[i];
    __syncthreads();
    int c = threadIdx.x % CC;
    int rloc = threadIdx.x / CC;
    int row = blockIdx.x * HEAD_ROWS + rloc;
    if (row >= Nrows) return;
    const float* a = &X[(size_t)row * DD];
    float acc = b[c];
#pragma unroll 8
    for (int k = 0; k < DD; k += 4) {
        float4 av = *(const float4*)&a[k];
        acc += av.x * Ws[(k + 0) * CC + c];
        acc += av.y * Ws[(k + 1) * CC + c];
        acc += av.z * Ws[(k + 2) * CC + c];
        acc += av.w * Ws[(k + 3) * CC + c];
    }
    Out[(size_t)row * CC + c] = acc;
}

// ---------------- driver ----------------
extern "C" void kernel_launch(void* const* d_in, const int* in_sizes, int n_in,
                              void* d_out, int out_size)
{
    const float* feat  = (const float*)d_in[0];
    const int*   src   = (const int*)d_in[1];
    const int*   dst   = (const int*)d_in[2];
    const float* W_fc  = (const float*)d_in[3];
    const float* b_fc  = (const float*)d_in[4];
    const float* W1    = (const float*)d_in[5];
    const float* b1    = (const float*)d_in[6];
    const float* W2    = (const float*)d_in[7];
    const float* b2    = (const float*)d_in[8];
    const float* W3    = (const float*)d_in[9];
    const float* b3    = (const float*)d_in[10];
    const float* gamma = (const float*)d_in[11];
    const float* beta  = (const float*)d_in[12];
    const float* W_lin = (const float*)d_in[13];
    const float* b_lin = (const float*)d_in[14];

    const int D = in_sizes[4];             // 256
    const int F = in_sizes[3] / D;         // 1024
    const int N = in_sizes[0] / F;         // 50000
    const int E = in_sizes[1];             // 300000

    float *p_norms, *p_normd, *p_XA, *p_XB, *p_sums, *p_sqs, *p_scale, *p_shift, *p_WT;
    int *p_odeg, *p_ideg, *p_offs, *p_cursor, *p_esrc;
    cudaGetSymbolAddress((void**)&p_norms, g_norms);
    cudaGetSymbolAddress((void**)&p_normd, g_normd);
    cudaGetSymbolAddress((void**)&p_odeg, g_odeg);
    cudaGetSymbolAddress((void**)&p_ideg, g_ideg);
    cudaGetSymbolAddress((void**)&p_offs, g_offs);
    cudaGetSymbolAddress((void**)&p_cursor, g_cursor);
    cudaGetSymbolAddress((void**)&p_esrc, g_esrc);
    cudaGetSymbolAddress((void**)&p_XA, g_XA);
    cudaGetSymbolAddress((void**)&p_XB, g_XB);
    cudaGetSymbolAddress((void**)&p_sums, g_sums);
    cudaGetSymbolAddress((void**)&p_sqs, g_sqs);
    cudaGetSymbolAddress((void**)&p_scale, g_scale);
    cudaGetSymbolAddress((void**)&p_shift, g_shift);
    cudaGetSymbolAddress((void**)&p_WT, g_WT);

    float* out_x = (float*)d_out;                       // [N, D]
    float* out_logits = (float*)d_out + (size_t)N * D;  // [N, C]

    float* WT_fc = p_WT;
    float* WT1 = p_WT + (size_t)D * F;
    float* WT2 = WT1 + (size_t)D * D;
    float* WT3 = WT2 + (size_t)D * D;

    // 0. transpose weights
    {
        dim3 blk(32, 8);
        transpose_kernel<<<dim3(F / 32, D / 32), blk>>>(W_fc, WT_fc, F, D);
        transpose_kernel<<<dim3(D / 32, D / 32), blk>>>(W1, WT1, D, D);
        transpose_kernel<<<dim3(D / 32, D / 32), blk>>>(W2, WT2, D, D);
        transpose_kernel<<<dim3(D / 32, D / 32), blk>>>(W3, WT3, D, D);
    }

    // 1. degrees -> norms + CSR
    cudaMemsetAsync(p_odeg, 0, N * sizeof(int));
    cudaMemsetAsync(p_ideg, 0, N * sizeof(int));
    deg_kernel<<<(E + 255) / 256, 256>>>(src, dst, p_odeg, p_ideg, E);
    norm_kernel<<<(N + 255) / 256, 256>>>(p_odeg, p_ideg, p_norms, p_normd, N);
    scan_kernel<<<1, SCAN_T>>>(p_ideg, p_offs, p_cursor, N);
    fill_kernel<<<(E + 255) / 256, 256>>>(src, dst, p_cursor, p_esrc, E);

    const int mblocks = (N + 127) / 128;
    dim3 ggrid(D / 128, mblocks);

    // 2. x = feat @ W_fc + b_fc -> XA
    mma_gemm<<<ggrid, 256>>>(feat, WT_fc, b_fc, nullptr, p_XA, N, F, D);

    const float* WTs[3] = {WT1, WT2, WT3};
    const float* bs[3] = {b1, b2, b3};
    long total = (long)N * D;

    for (int l = 0; l < 3; l++) {
        spmm_gather<<<(N + 3) / 4, 256>>>(p_XA, p_esrc, p_offs, p_norms, p_XB, N);
        float* dest = (l < 2) ? p_XA : out_x;
        mma_gemm<<<ggrid, 256>>>(p_XB, WTs[l], bs[l], p_normd, dest, N, D, D);
        if (l < 2) {
            cudaMemsetAsync(p_sums, 0, D * sizeof(float));
            cudaMemsetAsync(p_sqs, 0, D * sizeof(float));
            bn_stats_kernel<<<512, D>>>(p_XA, p_sums, p_sqs, N);
            bn_finalize_kernel<<<1, D>>>(p_sums, p_sqs, gamma, beta, p_scale, p_shift, N);
            bn_apply_elu_kernel<<<(int)((total + 255) / 256), 256>>>(p_XA, p_scale, p_shift, total);
        }
    }

    // 3. logits
    logits_kernel<<<(N + HEAD_ROWS - 1) / HEAD_ROWS, CC * HEAD_ROWS>>>(
        out_x, W_lin, b_lin, out_logits, N);
}

// round 5
// speedup vs baseline: 3.3241x; 1.5809x over previous
#include <cuda_runtime.h>
#include <cuda_fp16.h>
#include <math.h>
#include <stdint.h>

#define NN 50000
#define EE 300000
#define DD 256
#define FF 1024
#define CC 40

// ---------------- scratch (device globals) ----------------
__device__ float g_norms[NN];
__device__ float g_normd[NN];
__device__ int   g_odeg[NN];
__device__ int   g_ideg[NN];
__device__ int   g_offs[NN + 1];
__device__ int   g_cursor[NN];
__device__ int   g_esrc[EE];
__device__ __half g_HA[(size_t)NN * DD];   // fp16 activations
__device__ __half g_HB[(size_t)NN * DD];   // fp16 spmm output
__device__ float g_sums[DD];
__device__ float g_sqs[DD];
__device__ float g_scale[DD];
__device__ float g_shift[DD];
// fp16 transposed weights: WT_fc [256][1024], WT1/2/3 [256][256]
__device__ __half g_WT[(size_t)DD * FF + 3 * (size_t)DD * DD];

// ---------------- helpers ----------------
__device__ __forceinline__ uint32_t smem_u32(const void* p) {
    uint32_t a;
    asm("{ .reg .u64 t; cvta.to.shared.u64 t, %1; cvt.u32.u64 %0, t; }" : "=r"(a) : "l"(p));
    return a;
}
__device__ __forceinline__ uint32_t f22h(float a, float b) {
    __half2 h = __float22half2_rn(make_float2(a, b));
    return *(uint32_t*)&h;
}
__device__ __forceinline__ void ldsm4(uint32_t* r, uint32_t addr) {
    asm volatile("ldmatrix.sync.aligned.m8n8.x4.shared.b16 {%0,%1,%2,%3}, [%4];"
                 : "=r"(r[0]), "=r"(r[1]), "=r"(r[2]), "=r"(r[3]) : "r"(addr));
}
__device__ __forceinline__ void mma16816(float* c, const uint32_t* a, const uint32_t* b) {
    asm volatile(
        "mma.sync.aligned.m16n8k16.row.col.f32.f16.f16.f32 "
        "{%0,%1,%2,%3}, {%4,%5,%6,%7}, {%8,%9}, {%0,%1,%2,%3};"
        : "+f"(c[0]), "+f"(c[1]), "+f"(c[2]), "+f"(c[3])
        : "r"(a[0]), "r"(a[1]), "r"(a[2]), "r"(a[3]), "r"(b[0]), "r"(b[1]));
}

// swizzled half offset within a [rows][32] half tile (64B rows, 4x16B groups)
__device__ __forceinline__ int swoff(int r, int c) {
    return r * 32 + ((((c >> 3) ^ ((r >> 1) & 3)) << 3)) + (c & 7);
}

// ---------------- degree + norm ----------------
__global__ void deg_kernel(const int* __restrict__ src, const int* __restrict__ dst,
                           int* __restrict__ od, int* __restrict__ id, int E) {
    int t = blockIdx.x * blockDim.x + threadIdx.x;
    if (t >= E) return;
    atomicAdd(&od[src[t]], 1);
    atomicAdd(&id[dst[t]], 1);
}

__global__ void norm_kernel(const int* __restrict__ od, const int* __restrict__ id,
                            float* __restrict__ ns, float* __restrict__ nd, int n) {
    int t = blockIdx.x * blockDim.x + threadIdx.x;
    if (t >= n) return;
    ns[t] = rsqrtf(fmaxf((float)od[t], 1.0f));
    nd[t] = rsqrtf(fmaxf((float)id[t], 1.0f));
}

// ---------------- CSR build ----------------
#define SCAN_T 1024
__global__ void scan_kernel(const int* __restrict__ deg, int* __restrict__ offs,
                            int* __restrict__ cursor, int n) {
    __shared__ int sh[SCAN_T];
    int t = threadIdx.x;
    int chunk = (n + SCAN_T - 1) / SCAN_T;
    int a = t * chunk, b = min(a + chunk, n);
    int s = 0;
    for (int i = a; i < b; i++) s += deg[i];
    sh[t] = s;
    __syncthreads();
    for (int off = 1; off < SCAN_T; off <<= 1) {
        int v = (t >= off) ? sh[t - off] : 0;
        __syncthreads();
        sh[t] += v;
        __syncthreads();
    }
    int run = sh[t] - s;
    for (int i = a; i < b; i++) {
        offs[i] = run;
        cursor[i] = run;
        run += deg[i];
    }
    if (t == SCAN_T - 1) offs[n] = run;
}

__global__ void fill_kernel(const int* __restrict__ src, const int* __restrict__ dst,
                            int* __restrict__ cursor, int* __restrict__ esrc, int E) {
    int e = blockIdx.x * blockDim.x + threadIdx.x;
    if (e >= E) return;
    int p = atomicAdd(&cursor[dst[e]], 1);
    esrc[p] = src[e];
}

// ---------------- SpMM gather (fp16 in/out, fp32 accum, norm_d folded in) ----------------
__global__ __launch_bounds__(256) void spmm_gather_h(
    const __half* __restrict__ X, const int* __restrict__ esrc,
    const int* __restrict__ offs, const float* __restrict__ ns,
    const float* __restrict__ nd, __half* __restrict__ Out, int n)
{
    int row = blockIdx.x * 4 + (threadIdx.x >> 6);
    int lane = threadIdx.x & 63;
    if (row >= n) return;
    int o0 = offs[row], o1 = offs[row + 1];
    float4 acc = make_float4(0.f, 0.f, 0.f, 0.f);
    int i = o0;
    for (; i + 1 < o1; i += 2) {
        int s0 = __ldg(&esrc[i]), s1 = __ldg(&esrc[i + 1]);
        float c0 = __ldg(&ns[s0]), c1 = __ldg(&ns[s1]);
        uint2 u0 = *(const uint2*)&X[(size_t)s0 * DD + lane * 4];
        uint2 u1 = *(const uint2*)&X[(size_t)s1 * DD + lane * 4];
        float2 a0 = __half22float2(*(__half2*)&u0.x);
        float2 b0 = __half22float2(*(__half2*)&u0.y);
        float2 a1 = __half22float2(*(__half2*)&u1.x);
        float2 b1 = __half22float2(*(__half2*)&u1.y);
        acc.x += a0.x * c0 + a1.x * c1;
        acc.y += a0.y * c0 + a1.y * c1;
        acc.z += b0.x * c0 + b1.x * c1;
        acc.w += b0.y * c0 + b1.y * c1;
    }
    if (i < o1) {
        int s = __ldg(&esrc[i]);
        float c = __ldg(&ns[s]);
        uint2 u = *(const uint2*)&X[(size_t)s * DD + lane * 4];
        float2 a = __half22float2(*(__half2*)&u.x);
        float2 b = __half22float2(*(__half2*)&u.y);
        acc.x += a.x * c; acc.y += a.y * c;
        acc.z += b.x * c; acc.w += b.y * c;
    }
    float d = __ldg(&nd[row]);
    acc.x *= d; acc.y *= d; acc.z *= d; acc.w *= d;
    uint2 o;
    o.x = f22h(acc.x, acc.y);
    o.y = f22h(acc.z, acc.w);
    *(uint2*)&Out[(size_t)row * DD + lane * 4] = o;
}

// ---------------- weight transpose (fp32 -> fp16 transposed) ----------------
__global__ void transpose_kernel(const float* __restrict__ W, __half* __restrict__ Wt,
                                 int K, int Nn) {
    __shared__ float t[32][33];
    int bx = blockIdx.x * 32;  // K
    int by = blockIdx.y * 32;  // N
    int x = threadIdx.x, y = threadIdx.y;
    for (int j = 0; j < 32; j += 8)
        t[y + j][x] = W[(size_t)(bx + y + j) * Nn + by + x];
    __syncthreads();
    for (int j = 0; j < 32; j += 8)
        Wt[(size_t)(by + y + j) * K + bx + x] = __float2half_rn(t[x][y + j]);
}

// ---------------- fp16 mma GEMM ----------------
// C[M,256] = A[M,K] @ W + bias; Bt = fp16 W^T [256][K].
// Block 128x128, 256 threads, 8 warps (warp tile 64x32), double-buffered smem.
template <bool A_HALF, bool OUT_HALF>
__global__ __launch_bounds__(256, 2) void mma_gemm_t(
    const void* __restrict__ Ap, const __half* __restrict__ Bt,
    const float* __restrict__ bias, void* __restrict__ Cp,
    int M, int K, int Nn)
{
    __shared__ __align__(16) __half As[2][128 * 32];
    __shared__ __align__(16) __half Bs[2][128 * 32];

    const int tid = threadIdx.x;
    const int lane = tid & 31;
    const int warp = tid >> 5;
    const int wm = warp & 1;    // 64 rows
    const int wn = warp >> 1;   // 32 cols
    const int brow = blockIdx.y * 128;
    const int bcol = blockIdx.x * 128;
    const int l8 = lane & 7;
    const int q = lane >> 3;

    const float* Af = (const float*)Ap;
    const __half* Ah = (const __half*)Ap;

    float acc[4][4][4];
#pragma unroll
    for (int i = 0; i < 4; i++)
#pragma unroll
        for (int j = 0; j < 4; j++)
#pragma unroll
            for (int l = 0; l < 4; l++) acc[i][j][l] = 0.f;

    // load mappings
    int fR[4], fC[4];   // fp32 A: 4 x float4 (4 cols each)
#pragma unroll
    for (int i = 0; i < 4; i++) {
        int idx = tid + i * 256;
        fR[i] = idx >> 3;
        fC[i] = (idx & 7) << 2;
    }
    int hR[2], hC[2];   // fp16 tile: 2 x uint4 (8 cols each)
#pragma unroll
    for (int i = 0; i < 2; i++) {
        int idx = tid + i * 256;
        hR[i] = idx >> 2;
        hC[i] = (idx & 3) << 3;
    }

    const int nch = K >> 5;
    float4 ra[4];
    uint4 ha[2], hb[2];

    // ---- prologue: load chunk 0 to regs, store to smem[0]
    if (A_HALF) {
#pragma unroll
        for (int i = 0; i < 2; i++) {
            int gr = brow + hR[i];
            ha[i] = (gr < M) ? *(const uint4*)&Ah[(size_t)gr * K + hC[i]]
                             : make_uint4(0, 0, 0, 0);
        }
    } else {
#pragma unroll
        for (int i = 0; i < 4; i++) {
            int gr = brow + fR[i];
            ra[i] = (gr < M) ? *(const float4*)&Af[(size_t)gr * K + fC[i]]
                             : make_float4(0.f, 0.f, 0.f, 0.f);
        }
    }
#pragma unroll
    for (int i = 0; i < 2; i++)
        hb[i] = *(const uint4*)&Bt[(size_t)(bcol + hR[i]) * K + hC[i]];

    if (A_HALF) {
#pragma unroll
        for (int i = 0; i < 2; i++)
            *(uint4*)&As[0][swoff(hR[i], hC[i])] = ha[i];
    } else {
#pragma unroll
        for (int i = 0; i < 4; i++)
            *(uint2*)&As[0][swoff(fR[i], fC[i])] =
                make_uint2(f22h(ra[i].x, ra[i].y), f22h(ra[i].z, ra[i].w));
    }
#pragma unroll
    for (int i = 0; i < 2; i++)
        *(uint4*)&Bs[0][swoff(hR[i], hC[i])] = hb[i];
    __syncthreads();

    for (int c = 0; c < nch; c++) {
        const int buf = c & 1;
        if (c + 1 < nch) {
            int k0 = (c + 1) << 5;
            if (A_HALF) {
#pragma unroll
                for (int i = 0; i < 2; i++) {
                    int gr = brow + hR[i];
                    ha[i] = (gr < M) ? *(const uint4*)&Ah[(size_t)gr * K + k0 + hC[i]]
                                     : make_uint4(0, 0, 0, 0);
                }
            } else {
#pragma unroll
                for (int i = 0; i < 4; i++) {
                    int gr = brow + fR[i];
                    ra[i] = (gr < M) ? *(const float4*)&Af[(size_t)gr * K + k0 + fC[i]]
                                     : make_float4(0.f, 0.f, 0.f, 0.f);
                }
            }
#pragma unroll
            for (int i = 0; i < 2; i++)
                hb[i] = *(const uint4*)&Bt[(size_t)(bcol + hR[i]) * K + k0 + hC[i]];
        }

        // mma over smem[buf]: two k16 halves
#pragma unroll
        for (int kk = 0; kk < 2; kk++) {
            uint32_t af[4][4], bf[4][2];
#pragma unroll
            for (int mi = 0; mi < 4; mi++) {
                int row = wm * 64 + mi * 16 + ((q & 1) << 3) + l8;
                int col = kk * 16 + ((q >> 1) << 3);
                ldsm4(af[mi], smem_u32(&As[buf][swoff(row, col)]));
            }
#pragma unroll
            for (int p = 0; p < 2; p++) {
                int row = wn * 32 + p * 16 + ((q >> 1) << 3) + l8;
                int col = kk * 16 + ((q & 1) << 3);
                uint32_t r4[4];
                ldsm4(r4, smem_u32(&Bs[buf][swoff(row, col)]));
                bf[2 * p][0] = r4[0]; bf[2 * p][1] = r4[1];
                bf[2 * p + 1][0] = r4[2]; bf[2 * p + 1][1] = r4[3];
            }
#pragma unroll
            for (int mi = 0; mi < 4; mi++)
#pragma unroll
                for (int ni = 0; ni < 4; ni++)
                    mma16816(acc[mi][ni], af[mi], bf[ni]);
        }

        if (c + 1 < nch) {
            const int nb = buf ^ 1;
            if (A_HALF) {
#pragma unroll
                for (int i = 0; i < 2; i++)
                    *(uint4*)&As[nb][swoff(hR[i], hC[i])] = ha[i];
            } else {
#pragma unroll
                for (int i = 0; i < 4; i++)
                    *(uint2*)&As[nb][swoff(fR[i], fC[i])] =
                        make_uint2(f22h(ra[i].x, ra[i].y), f22h(ra[i].z, ra[i].w));
            }
#pragma unroll
            for (int i = 0; i < 2; i++)
                *(uint4*)&Bs[nb][swoff(hR[i], hC[i])] = hb[i];
        }
        __syncthreads();
    }

    // epilogue
    float* Cf = (float*)Cp;
    __half* Ch = (__half*)Cp;
#pragma unroll
    for (int mi = 0; mi < 4; mi++) {
        int r0 = brow + wm * 64 + mi * 16 + (lane >> 2);
#pragma unroll
        for (int ni = 0; ni < 4; ni++) {
            int cc = bcol + wn * 32 + ni * 8 + (lane & 3) * 2;
            float b0 = bias[cc], b1 = bias[cc + 1];
            if (r0 < M) {
                float v0 = acc[mi][ni][0] + b0, v1 = acc[mi][ni][1] + b1;
                if (OUT_HALF) *(uint32_t*)&Ch[(size_t)r0 * Nn + cc] = f22h(v0, v1);
                else *(float2*)&Cf[(size_t)r0 * Nn + cc] = make_float2(v0, v1);
            }
            if (r0 + 8 < M) {
                float v0 = acc[mi][ni][2] + b0, v1 = acc[mi][ni][3] + b1;
                if (OUT_HALF) *(uint32_t*)&Ch[(size_t)(r0 + 8) * Nn + cc] = f22h(v0, v1);
                else *(float2*)&Cf[(size_t)(r0 + 8) * Nn + cc] = make_float2(v0, v1);
            }
        }
    }
}

// ---------------- batchnorm (fp16 storage, fp32 math) ----------------
__global__ void bn_stats_h(const __half* __restrict__ X, float* __restrict__ sums,
                           float* __restrict__ sqs, int Nrows)
{
    int col2 = threadIdx.x;          // 128 threads, each a half2 column pair
    int rows_per = (Nrows + gridDim.x - 1) / gridDim.x;
    int r0 = blockIdx.x * rows_per;
    int r1 = min(r0 + rows_per, Nrows);
    float s0 = 0.f, s1 = 0.f, q0 = 0.f, q1 = 0.f;
    const __half2* X2 = (const __half2*)X;
    for (int r = r0; r < r1; r++) {
        float2 v = __half22float2(X2[(size_t)r * (DD / 2) + col2]);
        s0 += v.x; s1 += v.y;
        q0 += v.x * v.x; q1 += v.y * v.y;
    }
    atomicAdd(&sums[col2 * 2 + 0], s0);
    atomicAdd(&sums[col2 * 2 + 1], s1);
    atomicAdd(&sqs[col2 * 2 + 0], q0);
    atomicAdd(&sqs[col2 * 2 + 1], q1);
}

__global__ void bn_finalize_kernel(const float* __restrict__ sums, const float* __restrict__ sqs,
                                   const float* __restrict__ gamma, const float* __restrict__ beta,
                                   float* __restrict__ scale, float* __restrict__ shift, int Nrows)
{
    int c = threadIdx.x;
    float invn = 1.0f / (float)Nrows;
    float mu = sums[c] * invn;
    float var = sqs[c] * invn - mu * mu;
    float inv = rsqrtf(var + 1e-5f);
    float sc = gamma[c] * inv;
    scale[c] = sc;
    shift[c] = beta[c] - mu * sc;
}

__global__ void bn_apply_elu_h(__half* __restrict__ X, const float* __restrict__ scale,
                               const float* __restrict__ shift, long total2)
{
    long t = (long)blockIdx.x * blockDim.x + threadIdx.x;
    if (t >= total2) return;
    int col2 = (int)(t & (DD / 2 - 1));
    __half2* X2 = (__half2*)X;
    float2 v = __half22float2(X2[t]);
    float y0 = v.x * scale[col2 * 2] + shift[col2 * 2];
    float y1 = v.y * scale[col2 * 2 + 1] + shift[col2 * 2 + 1];
    y0 = (y0 > 0.f) ? y0 : expm1f(y0);
    y1 = (y1 > 0.f) ? y1 : expm1f(y1);
    X2[t] = __floats2half2_rn(y0, y1);
}

// ---------------- classifier head ----------------
#define HEAD_ROWS 8
__global__ __launch_bounds__(CC * HEAD_ROWS) void logits_kernel(
    const float* __restrict__ X, const float* __restrict__ W,
    const float* __restrict__ b, float* __restrict__ Out, int Nrows)
{
    __shared__ float Ws[DD * CC];
    for (int i = threadIdx.x; i < DD * CC; i += blockDim.x) Ws[i] = W[i];
    __syncthreads();
    int c = threadIdx.x % CC;
    int rloc = threadIdx.x / CC;
    int row = blockIdx.x * HEAD_ROWS + rloc;
    if (row >= Nrows) return;
    const float* a = &X[(size_t)row * DD];
    float acc = b[c];
#pragma unroll 8
    for (int k = 0; k < DD; k += 4) {
        float4 av = *(const float4*)&a[k];
        acc += av.x * Ws[(k + 0) * CC + c];
        acc += av.y * Ws[(k + 1) * CC + c];
        acc += av.z * Ws[(k + 2) * CC + c];
        acc += av.w * Ws[(k + 3) * CC + c];
    }
    Out[(size_t)row * CC + c] = acc;
}

// ---------------- driver ----------------
extern "C" void kernel_launch(void* const* d_in, const int* in_sizes, int n_in,
                              void* d_out, int out_size)
{
    const float* feat  = (const float*)d_in[0];
    const int*   src   = (const int*)d_in[1];
    const int*   dst   = (const int*)d_in[2];
    const float* W_fc  = (const float*)d_in[3];
    const float* b_fc  = (const float*)d_in[4];
    const float* W1    = (const float*)d_in[5];
    const float* b1    = (const float*)d_in[6];
    const float* W2    = (const float*)d_in[7];
    const float* b2    = (const float*)d_in[8];
    const float* W3    = (const float*)d_in[9];
    const float* b3    = (const float*)d_in[10];
    const float* gamma = (const float*)d_in[11];
    const float* beta  = (const float*)d_in[12];
    const float* W_lin = (const float*)d_in[13];
    const float* b_lin = (const float*)d_in[14];

    const int D = in_sizes[4];             // 256
    const int F = in_sizes[3] / D;         // 1024
    const int N = in_sizes[0] / F;         // 50000
    const int E = in_sizes[1];             // 300000

    float *p_norms, *p_normd, *p_sums, *p_sqs, *p_scale, *p_shift;
    int *p_odeg, *p_ideg, *p_offs, *p_cursor, *p_esrc;
    __half *p_HA, *p_HB, *p_WT;
    cudaGetSymbolAddress((void**)&p_norms, g_norms);
    cudaGetSymbolAddress((void**)&p_normd, g_normd);
    cudaGetSymbolAddress((void**)&p_odeg, g_odeg);
    cudaGetSymbolAddress((void**)&p_ideg, g_ideg);
    cudaGetSymbolAddress((void**)&p_offs, g_offs);
    cudaGetSymbolAddress((void**)&p_cursor, g_cursor);
    cudaGetSymbolAddress((void**)&p_esrc, g_esrc);
    cudaGetSymbolAddress((void**)&p_HA, g_HA);
    cudaGetSymbolAddress((void**)&p_HB, g_HB);
    cudaGetSymbolAddress((void**)&p_sums, g_sums);
    cudaGetSymbolAddress((void**)&p_sqs, g_sqs);
    cudaGetSymbolAddress((void**)&p_scale, g_scale);
    cudaGetSymbolAddress((void**)&p_shift, g_shift);
    cudaGetSymbolAddress((void**)&p_WT, g_WT);

    float* out_x = (float*)d_out;                       // [N, D]
    float* out_logits = (float*)d_out + (size_t)N * D;  // [N, C]

    __half* WT_fc = p_WT;
    __half* WT1 = p_WT + (size_t)D * F;
    __half* WT2 = WT1 + (size_t)D * D;
    __half* WT3 = WT2 + (size_t)D * D;

    // 0. transpose + fp16-convert weights
    {
        dim3 blk(32, 8);
        transpose_kernel<<<dim3(F / 32, D / 32), blk>>>(W_fc, WT_fc, F, D);
        transpose_kernel<<<dim3(D / 32, D / 32), blk>>>(W1, WT1, D, D);
        transpose_kernel<<<dim3(D / 32, D / 32), blk>>>(W2, WT2, D, D);
        transpose_kernel<<<dim3(D / 32, D / 32), blk>>>(W3, WT3, D, D);
    }

    // 1. degrees -> norms + CSR
    cudaMemsetAsync(p_odeg, 0, N * sizeof(int));
    cudaMemsetAsync(p_ideg, 0, N * sizeof(int));
    deg_kernel<<<(E + 255) / 256, 256>>>(src, dst, p_odeg, p_ideg, E);
    norm_kernel<<<(N + 255) / 256, 256>>>(p_odeg, p_ideg, p_norms, p_normd, N);
    scan_kernel<<<1, SCAN_T>>>(p_ideg, p_offs, p_cursor, N);
    fill_kernel<<<(E + 255) / 256, 256>>>(src, dst, p_cursor, p_esrc, E);

    const int mblocks = (N + 127) / 128;
    dim3 ggrid(D / 128, mblocks);

    // 2. x = feat @ W_fc + b_fc -> HA (fp16)
    mma_gemm_t<false, true><<<ggrid, 256>>>(feat, WT_fc, b_fc, p_HA, N, F, D);

    const __half* WTs[3] = {WT1, WT2, WT3};
    const float* bs[3] = {b1, b2, b3};
    long total2 = (long)N * D / 2;

    for (int l = 0; l < 3; l++) {
        spmm_gather_h<<<(N + 3) / 4, 256>>>(p_HA, p_esrc, p_offs, p_norms, p_normd, p_HB, N);
        if (l < 2) {
            mma_gemm_t<true, true><<<ggrid, 256>>>(p_HB, WTs[l], bs[l], p_HA, N, D, D);
            cudaMemsetAsync(p_sums, 0, D * sizeof(float));
            cudaMemsetAsync(p_sqs, 0, D * sizeof(float));
            bn_stats_h<<<512, D / 2>>>(p_HA, p_sums, p_sqs, N);
            bn_finalize_kernel<<<1, D>>>(p_sums, p_sqs, gamma, beta, p_scale, p_shift, N);
            bn_apply_elu_h<<<(int)((total2 + 255) / 256), 256>>>(p_HA, p_scale, p_shift, total2);
        } else {
            mma_gemm_t<true, false><<<ggrid, 256>>>(p_HB, WTs[l], bs[l], out_x, N, D, D);
        }
    }

    // 3. logits
    logits_kernel<<<(N + HEAD_ROWS - 1) / HEAD_ROWS, CC * HEAD_ROWS>>>(
        out_x, W_lin, b_lin, out_logits, N);
}

// round 6
// speedup vs baseline: 3.4399x; 1.0348x over previous
#include <cuda_runtime.h>
#include <cuda_fp16.h>
#include <math.h>
#include <stdint.h>

#define NN 50000
#define EE 300000
#define DD 256
#define FF 1024
#define CC 40

// ---------------- scratch (device globals) ----------------
__device__ float g_norms[NN];
__device__ float g_normd[NN];
__device__ int   g_odeg[NN];
__device__ int   g_ideg[NN];
__device__ int   g_offs[NN + 1];
__device__ int   g_cursor[NN];
__device__ int   g_esrc[EE];
__device__ __half g_HA[(size_t)NN * DD];   // fp16 activations
__device__ __half g_HB[(size_t)NN * DD];   // fp16 spmm output
__device__ float g_sums[DD];
__device__ float g_sqs[DD];
__device__ float g_scale[DD];
__device__ float g_shift[DD];
// fp16 transposed weights: WT_fc [256][1024], WT1/2/3 [256][256]
__device__ __half g_WT[(size_t)DD * FF + 3 * (size_t)DD * DD];

// ---------------- helpers ----------------
__device__ __forceinline__ uint32_t smem_u32(const void* p) {
    uint32_t a;
    asm("{ .reg .u64 t; cvta.to.shared.u64 t, %1; cvt.u32.u64 %0, t; }" : "=r"(a) : "l"(p));
    return a;
}
__device__ __forceinline__ uint32_t f22h(float a, float b) {
    __half2 h = __float22half2_rn(make_float2(a, b));
    return *(uint32_t*)&h;
}
__device__ __forceinline__ void ldsm4(uint32_t* r, uint32_t addr) {
    asm volatile("ldmatrix.sync.aligned.m8n8.x4.shared.b16 {%0,%1,%2,%3}, [%4];"
                 : "=r"(r[0]), "=r"(r[1]), "=r"(r[2]), "=r"(r[3]) : "r"(addr));
}
__device__ __forceinline__ void mma16816(float* c, const uint32_t* a, const uint32_t* b) {
    asm volatile(
        "mma.sync.aligned.m16n8k16.row.col.f32.f16.f16.f32 "
        "{%0,%1,%2,%3}, {%4,%5,%6,%7}, {%8,%9}, {%0,%1,%2,%3};"
        : "+f"(c[0]), "+f"(c[1]), "+f"(c[2]), "+f"(c[3])
        : "r"(a[0]), "r"(a[1]), "r"(a[2]), "r"(a[3]), "r"(b[0]), "r"(b[1]));
}

// swizzled half offset within a [rows][32] half tile (64B rows, 4x16B groups)
__device__ __forceinline__ int swoff(int r, int c) {
    return r * 32 + ((((c >> 3) ^ ((r >> 1) & 3)) << 3)) + (c & 7);
}

// ---------------- degree + norm ----------------
__global__ void deg_kernel(const int* __restrict__ src, const int* __restrict__ dst,
                           int* __restrict__ od, int* __restrict__ id, int E) {
    int t = blockIdx.x * blockDim.x + threadIdx.x;
    if (t >= E) return;
    atomicAdd(&od[src[t]], 1);
    atomicAdd(&id[dst[t]], 1);
}

__global__ void norm_kernel(const int* __restrict__ od, const int* __restrict__ id,
                            float* __restrict__ ns, float* __restrict__ nd, int n) {
    int t = blockIdx.x * blockDim.x + threadIdx.x;
    if (t >= n) return;
    ns[t] = rsqrtf(fmaxf((float)od[t], 1.0f));
    nd[t] = rsqrtf(fmaxf((float)id[t], 1.0f));
}

// ---------------- CSR build ----------------
#define SCAN_T 1024
__global__ void scan_kernel(const int* __restrict__ deg, int* __restrict__ offs,
                            int* __restrict__ cursor, int n) {
    __shared__ int sh[SCAN_T];
    int t = threadIdx.x;
    int chunk = (n + SCAN_T - 1) / SCAN_T;
    int a = t * chunk, b = min(a + chunk, n);
    int s = 0;
    for (int i = a; i < b; i++) s += deg[i];
    sh[t] = s;
    __syncthreads();
    for (int off = 1; off < SCAN_T; off <<= 1) {
        int v = (t >= off) ? sh[t - off] : 0;
        __syncthreads();
        sh[t] += v;
        __syncthreads();
    }
    int run = sh[t] - s;
    for (int i = a; i < b; i++) {
        offs[i] = run;
        cursor[i] = run;
        run += deg[i];
    }
    if (t == SCAN_T - 1) offs[n] = run;
}

__global__ void fill_kernel(const int* __restrict__ src, const int* __restrict__ dst,
                            int* __restrict__ cursor, int* __restrict__ esrc, int E) {
    int e = blockIdx.x * blockDim.x + threadIdx.x;
    if (e >= E) return;
    int p = atomicAdd(&cursor[dst[e]], 1);
    esrc[p] = src[e];
}

// ---------------- SpMM gather (fp16 in/out, fp32 accum, norm_d folded in) ----------------
// 32 threads/row (uint4 = 8 halves each), 8 rows/block, 4-edge unroll for MLP.
__global__ __launch_bounds__(256) void spmm_gather_h(
    const __half* __restrict__ X, const int* __restrict__ esrc,
    const int* __restrict__ offs, const float* __restrict__ ns,
    const float* __restrict__ nd, __half* __restrict__ Out, int n)
{
    int row = blockIdx.x * 8 + (threadIdx.x >> 5);
    int lane = threadIdx.x & 31;
    if (row >= n) return;
    int o0 = offs[row], o1 = offs[row + 1];
    float acc[8];
#pragma unroll
    for (int k = 0; k < 8; k++) acc[k] = 0.f;

    int i = o0;
    for (; i + 4 <= o1; i += 4) {
        int s[4];
        float c[4];
        uint4 u[4];
#pragma unroll
        for (int j = 0; j < 4; j++) s[j] = __ldg(&esrc[i + j]);
#pragma unroll
        for (int j = 0; j < 4; j++) {
            c[j] = __ldg(&ns[s[j]]);
            u[j] = *(const uint4*)&X[(size_t)s[j] * DD + lane * 8];
        }
#pragma unroll
        for (int j = 0; j < 4; j++) {
            const __half2* h = (const __half2*)&u[j];
#pragma unroll
            for (int k = 0; k < 4; k++) {
                float2 v = __half22float2(h[k]);
                acc[2 * k] += v.x * c[j];
                acc[2 * k + 1] += v.y * c[j];
            }
        }
    }
    for (; i < o1; i++) {
        int s = __ldg(&esrc[i]);
        float c = __ldg(&ns[s]);
        uint4 u = *(const uint4*)&X[(size_t)s * DD + lane * 8];
        const __half2* h = (const __half2*)&u;
#pragma unroll
        for (int k = 0; k < 4; k++) {
            float2 v = __half22float2(h[k]);
            acc[2 * k] += v.x * c;
            acc[2 * k + 1] += v.y * c;
        }
    }
    float d = __ldg(&nd[row]);
    uint4 o;
    uint32_t* ow = (uint32_t*)&o;
#pragma unroll
    for (int k = 0; k < 4; k++)
        ow[k] = f22h(acc[2 * k] * d, acc[2 * k + 1] * d);
    *(uint4*)&Out[(size_t)row * DD + lane * 8] = o;
}

// ---------------- weight transpose (fp32 -> fp16 transposed) ----------------
__global__ void transpose_kernel(const float* __restrict__ W, __half* __restrict__ Wt,
                                 int K, int Nn) {
    __shared__ float t[32][33];
    int bx = blockIdx.x * 32;  // K
    int by = blockIdx.y * 32;  // N
    int x = threadIdx.x, y = threadIdx.y;
    for (int j = 0; j < 32; j += 8)
        t[y + j][x] = W[(size_t)(bx + y + j) * Nn + by + x];
    __syncthreads();
    for (int j = 0; j < 32; j += 8)
        Wt[(size_t)(by + y + j) * K + bx + x] = __float2half_rn(t[x][y + j]);
}

// ---------------- fp16 mma GEMM, single-pass 128x256 block tile ----------------
// C[M,256] = A[M,K] @ W + bias; Bt = fp16 W^T [256][K]. Nn fixed = 256.
// 256 threads, 8 warps, warp tile 64x64, acc[4][8][4]; grid (1, ceil(M/128)).
template <bool A_HALF, bool OUT_HALF>
__global__ __launch_bounds__(256, 1) void mma_gemm_t(
    const void* __restrict__ Ap, const __half* __restrict__ Bt,
    const float* __restrict__ bias, void* __restrict__ Cp,
    int M, int K)
{
    __shared__ __align__(16) __half As[2][128 * 32];
    __shared__ __align__(16) __half Bs[2][256 * 32];

    const int tid = threadIdx.x;
    const int lane = tid & 31;
    const int warp = tid >> 5;
    const int wm = warp & 1;    // 64-row half
    const int wn = warp >> 1;   // 64-col quarter
    const int brow = blockIdx.y * 128;
    const int l8 = lane & 7;
    const int q = lane >> 3;

    const float* Af = (const float*)Ap;
    const __half* Ah = (const __half*)Ap;

    float acc[4][8][4];
#pragma unroll
    for (int i = 0; i < 4; i++)
#pragma unroll
        for (int j = 0; j < 8; j++)
#pragma unroll
            for (int l = 0; l < 4; l++) acc[i][j][l] = 0.f;

    // load mappings
    int fR[4], fC[4];   // fp32 A: 4 x float4
#pragma unroll
    for (int i = 0; i < 4; i++) {
        int idx = tid + i * 256;
        fR[i] = idx >> 3;
        fC[i] = (idx & 7) << 2;
    }
    int hR[2], hC[2];   // fp16 A: 2 x uint4
#pragma unroll
    for (int i = 0; i < 2; i++) {
        int idx = tid + i * 256;
        hR[i] = idx >> 2;
        hC[i] = (idx & 3) << 3;
    }
    int bR[4], bC[4];   // B: 4 x uint4 over 256 rows
#pragma unroll
    for (int i = 0; i < 4; i++) {
        int idx = tid + i * 256;
        bR[i] = idx >> 2;
        bC[i] = (idx & 3) << 3;
    }

    const int nch = K >> 5;
    float4 ra[4];
    uint4 ha[2], hb[4];

    // ---- prologue: load chunk 0, store to smem[0]
    if (A_HALF) {
#pragma unroll
        for (int i = 0; i < 2; i++) {
            int gr = brow + hR[i];
            ha[i] = (gr < M) ? *(const uint4*)&Ah[(size_t)gr * K + hC[i]]
                             : make_uint4(0, 0, 0, 0);
        }
    } else {
#pragma unroll
        for (int i = 0; i < 4; i++) {
            int gr = brow + fR[i];
            ra[i] = (gr < M) ? *(const float4*)&Af[(size_t)gr * K + fC[i]]
                             : make_float4(0.f, 0.f, 0.f, 0.f);
        }
    }
#pragma unroll
    for (int i = 0; i < 4; i++)
        hb[i] = *(const uint4*)&Bt[(size_t)bR[i] * K + bC[i]];

    if (A_HALF) {
#pragma unroll
        for (int i = 0; i < 2; i++)
            *(uint4*)&As[0][swoff(hR[i], hC[i])] = ha[i];
    } else {
#pragma unroll
        for (int i = 0; i < 4; i++)
            *(uint2*)&As[0][swoff(fR[i], fC[i])] =
                make_uint2(f22h(ra[i].x, ra[i].y), f22h(ra[i].z, ra[i].w));
    }
#pragma unroll
    for (int i = 0; i < 4; i++)
        *(uint4*)&Bs[0][swoff(bR[i], bC[i])] = hb[i];
    __syncthreads();

    for (int c = 0; c < nch; c++) {
        const int buf = c & 1;
        if (c + 1 < nch) {
            int k0 = (c + 1) << 5;
            if (A_HALF) {
#pragma unroll
                for (int i = 0; i < 2; i++) {
                    int gr = brow + hR[i];
                    ha[i] = (gr < M) ? *(const uint4*)&Ah[(size_t)gr * K + k0 + hC[i]]
                                     : make_uint4(0, 0, 0, 0);
                }
            } else {
#pragma unroll
                for (int i = 0; i < 4; i++) {
                    int gr = brow + fR[i];
                    ra[i] = (gr < M) ? *(const float4*)&Af[(size_t)gr * K + k0 + fC[i]]
                                     : make_float4(0.f, 0.f, 0.f, 0.f);
                }
            }
#pragma unroll
            for (int i = 0; i < 4; i++)
                hb[i] = *(const uint4*)&Bt[(size_t)bR[i] * K + k0 + bC[i]];
        }

        // mma over smem[buf]: two k16 halves
#pragma unroll
        for (int kk = 0; kk < 2; kk++) {
            uint32_t af[4][4], bf[8][2];
#pragma unroll
            for (int mi = 0; mi < 4; mi++) {
                int row = wm * 64 + mi * 16 + ((q & 1) << 3) + l8;
                int col = kk * 16 + ((q >> 1) << 3);
                ldsm4(af[mi], smem_u32(&As[buf][swoff(row, col)]));
            }
#pragma unroll
            for (int p = 0; p < 4; p++) {
                int row = wn * 64 + p * 16 + ((q >> 1) << 3) + l8;
                int col = kk * 16 + ((q & 1) << 3);
                uint32_t r4[4];
                ldsm4(r4, smem_u32(&Bs[buf][swoff(row, col)]));
                bf[2 * p][0] = r4[0]; bf[2 * p][1] = r4[1];
                bf[2 * p + 1][0] = r4[2]; bf[2 * p + 1][1] = r4[3];
            }
#pragma unroll
            for (int mi = 0; mi < 4; mi++)
#pragma unroll
                for (int ni = 0; ni < 8; ni++)
                    mma16816(acc[mi][ni], af[mi], bf[ni]);
        }

        if (c + 1 < nch) {
            const int nb = buf ^ 1;
            if (A_HALF) {
#pragma unroll
                for (int i = 0; i < 2; i++)
                    *(uint4*)&As[nb][swoff(hR[i], hC[i])] = ha[i];
            } else {
#pragma unroll
                for (int i = 0; i < 4; i++)
                    *(uint2*)&As[nb][swoff(fR[i], fC[i])] =
                        make_uint2(f22h(ra[i].x, ra[i].y), f22h(ra[i].z, ra[i].w));
            }
#pragma unroll
            for (int i = 0; i < 4; i++)
                *(uint4*)&Bs[nb][swoff(bR[i], bC[i])] = hb[i];
        }
        __syncthreads();
    }

    // epilogue
    float* Cf = (float*)Cp;
    __half* Ch = (__half*)Cp;
#pragma unroll
    for (int mi = 0; mi < 4; mi++) {
        int r0 = brow + wm * 64 + mi * 16 + (lane >> 2);
#pragma unroll
        for (int ni = 0; ni < 8; ni++) {
            int cc = wn * 64 + ni * 8 + (lane & 3) * 2;
            float b0 = bias[cc], b1 = bias[cc + 1];
            if (r0 < M) {
                float v0 = acc[mi][ni][0] + b0, v1 = acc[mi][ni][1] + b1;
                if (OUT_HALF) *(uint32_t*)&Ch[(size_t)r0 * 256 + cc] = f22h(v0, v1);
                else *(float2*)&Cf[(size_t)r0 * 256 + cc] = make_float2(v0, v1);
            }
            if (r0 + 8 < M) {
                float v0 = acc[mi][ni][2] + b0, v1 = acc[mi][ni][3] + b1;
                if (OUT_HALF) *(uint32_t*)&Ch[(size_t)(r0 + 8) * 256 + cc] = f22h(v0, v1);
                else *(float2*)&Cf[(size_t)(r0 + 8) * 256 + cc] = make_float2(v0, v1);
            }
        }
    }
}

// ---------------- batchnorm (fp16 storage, fp32 math) ----------------
__global__ void bn_stats_h(const __half* __restrict__ X, float* __restrict__ sums,
                           float* __restrict__ sqs, int Nrows)
{
    int col2 = threadIdx.x;
    int rows_per = (Nrows + gridDim.x - 1) / gridDim.x;
    int r0 = blockIdx.x * rows_per;
    int r1 = min(r0 + rows_per, Nrows);
    float s0 = 0.f, s1 = 0.f, q0 = 0.f, q1 = 0.f;
    const __half2* X2 = (const __half2*)X;
    for (int r = r0; r < r1; r++) {
        float2 v = __half22float2(X2[(size_t)r * (DD / 2) + col2]);
        s0 += v.x; s1 += v.y;
        q0 += v.x * v.x; q1 += v.y * v.y;
    }
    atomicAdd(&sums[col2 * 2 + 0], s0);
    atomicAdd(&sums[col2 * 2 + 1], s1);
    atomicAdd(&sqs[col2 * 2 + 0], q0);
    atomicAdd(&sqs[col2 * 2 + 1], q1);
}

__global__ void bn_finalize_kernel(const float* __restrict__ sums, const float* __restrict__ sqs,
                                   const float* __restrict__ gamma, const float* __restrict__ beta,
                                   float* __restrict__ scale, float* __restrict__ shift, int Nrows)
{
    int c = threadIdx.x;
    float invn = 1.0f / (float)Nrows;
    float mu = sums[c] * invn;
    float var = sqs[c] * invn - mu * mu;
    float inv = rsqrtf(var + 1e-5f);
    float sc = gamma[c] * inv;
    scale[c] = sc;
    shift[c] = beta[c] - mu * sc;
}

__global__ void bn_apply_elu_h(__half* __restrict__ X, const float* __restrict__ scale,
                               const float* __restrict__ shift, long total2)
{
    long t = (long)blockIdx.x * blockDim.x + threadIdx.x;
    if (t >= total2) return;
    int col2 = (int)(t & (DD / 2 - 1));
    __half2* X2 = (__half2*)X;
    float2 v = __half22float2(X2[t]);
    float y0 = v.x * scale[col2 * 2] + shift[col2 * 2];
    float y1 = v.y * scale[col2 * 2 + 1] + shift[col2 * 2 + 1];
    y0 = (y0 > 0.f) ? y0 : expm1f(y0);
    y1 = (y1 > 0.f) ? y1 : expm1f(y1);
    X2[t] = __floats2half2_rn(y0, y1);
}

// ---------------- classifier head ----------------
#define HEAD_ROWS 8
__global__ __launch_bounds__(CC * HEAD_ROWS) void logits_kernel(
    const float* __restrict__ X, const float* __restrict__ W,
    const float* __restrict__ b, float* __restrict__ Out, int Nrows)
{
    __shared__ float Ws[DD * CC];
    for (int i = threadIdx.x; i < DD * CC; i += blockDim.x) Ws[i] = W[i];
    __syncthreads();
    int c = threadIdx.x % CC;
    int rloc = threadIdx.x / CC;
    int row = blockIdx.x * HEAD_ROWS + rloc;
    if (row >= Nrows) return;
    const float* a = &X[(size_t)row * DD];
    float acc = b[c];
#pragma unroll 8
    for (int k = 0; k < DD; k += 4) {
        float4 av = *(const float4*)&a[k];
        acc += av.x * Ws[(k + 0) * CC + c];
        acc += av.y * Ws[(k + 1) * CC + c];
        acc += av.z * Ws[(k + 2) * CC + c];
        acc += av.w * Ws[(k + 3) * CC + c];
    }
    Out[(size_t)row * CC + c] = acc;
}

// ---------------- driver ----------------
extern "C" void kernel_launch(void* const* d_in, const int* in_sizes, int n_in,
                              void* d_out, int out_size)
{
    const float* feat  = (const float*)d_in[0];
    const int*   src   = (const int*)d_in[1];
    const int*   dst   = (const int*)d_in[2];
    const float* W_fc  = (const float*)d_in[3];
    const float* b_fc  = (const float*)d_in[4];
    const float* W1    = (const float*)d_in[5];
    const float* b1    = (const float*)d_in[6];
    const float* W2    = (const float*)d_in[7];
    const float* b2    = (const float*)d_in[8];
    const float* W3    = (const float*)d_in[9];
    const float* b3    = (const float*)d_in[10];
    const float* gamma = (const float*)d_in[11];
    const float* beta  = (const float*)d_in[12];
    const float* W_lin = (const float*)d_in[13];
    const float* b_lin = (const float*)d_in[14];

    const int D = in_sizes[4];             // 256
    const int F = in_sizes[3] / D;         // 1024
    const int N = in_sizes[0] / F;         // 50000
    const int E = in_sizes[1];             // 300000

    float *p_norms, *p_normd, *p_sums, *p_sqs, *p_scale, *p_shift;
    int *p_odeg, *p_ideg, *p_offs, *p_cursor, *p_esrc;
    __half *p_HA, *p_HB, *p_WT;
    cudaGetSymbolAddress((void**)&p_norms, g_norms);
    cudaGetSymbolAddress((void**)&p_normd, g_normd);
    cudaGetSymbolAddress((void**)&p_odeg, g_odeg);
    cudaGetSymbolAddress((void**)&p_ideg, g_ideg);
    cudaGetSymbolAddress((void**)&p_offs, g_offs);
    cudaGetSymbolAddress((void**)&p_cursor, g_cursor);
    cudaGetSymbolAddress((void**)&p_esrc, g_esrc);
    cudaGetSymbolAddress((void**)&p_HA, g_HA);
    cudaGetSymbolAddress((void**)&p_HB, g_HB);
    cudaGetSymbolAddress((void**)&p_sums, g_sums);
    cudaGetSymbolAddress((void**)&p_sqs, g_sqs);
    cudaGetSymbolAddress((void**)&p_scale, g_scale);
    cudaGetSymbolAddress((void**)&p_shift, g_shift);
    cudaGetSymbolAddress((void**)&p_WT, g_WT);

    float* out_x = (float*)d_out;                       // [N, D]
    float* out_logits = (float*)d_out + (size_t)N * D;  // [N, C]

    __half* WT_fc = p_WT;
    __half* WT1 = p_WT + (size_t)D * F;
    __half* WT2 = WT1 + (size_t)D * D;
    __half* WT3 = WT2 + (size_t)D * D;

    // 0. transpose + fp16-convert weights
    {
        dim3 blk(32, 8);
        transpose_kernel<<<dim3(F / 32, D / 32), blk>>>(W_fc, WT_fc, F, D);
        transpose_kernel<<<dim3(D / 32, D / 32), blk>>>(W1, WT1, D, D);
        transpose_kernel<<<dim3(D / 32, D / 32), blk>>>(W2, WT2, D, D);
        transpose_kernel<<<dim3(D / 32, D / 32), blk>>>(W3, WT3, D, D);
    }

    // 1. degrees -> norms + CSR
    cudaMemsetAsync(p_odeg, 0, N * sizeof(int));
    cudaMemsetAsync(p_ideg, 0, N * sizeof(int));
    deg_kernel<<<(E + 255) / 256, 256>>>(src, dst, p_odeg, p_ideg, E);
    norm_kernel<<<(N + 255) / 256, 256>>>(p_odeg, p_ideg, p_norms, p_normd, N);
    scan_kernel<<<1, SCAN_T>>>(p_ideg, p_offs, p_cursor, N);
    fill_kernel<<<(E + 255) / 256, 256>>>(src, dst, p_cursor, p_esrc, E);

    const int mblocks = (N + 127) / 128;
    dim3 ggrid(1, mblocks);

    // 2. x = feat @ W_fc + b_fc -> HA (fp16)
    mma_gemm_t<false, true><<<ggrid, 256>>>(feat, WT_fc, b_fc, p_HA, N, F);

    const __half* WTs[3] = {WT1, WT2, WT3};
    const float* bs[3] = {b1, b2, b3};
    long total2 = (long)N * D / 2;

    for (int l = 0; l < 3; l++) {
        spmm_gather_h<<<(N + 7) / 8, 256>>>(p_HA, p_esrc, p_offs, p_norms, p_normd, p_HB, N);
        if (l < 2) {
            mma_gemm_t<true, true><<<ggrid, 256>>>(p_HB, WTs[l], bs[l], p_HA, N, D);
            cudaMemsetAsync(p_sums, 0, D * sizeof(float));
            cudaMemsetAsync(p_sqs, 0, D * sizeof(float));
            bn_stats_h<<<512, D / 2>>>(p_HA, p_sums, p_sqs, N);
            bn_finalize_kernel<<<1, D>>>(p_sums, p_sqs, gamma, beta, p_scale, p_shift, N);
            bn_apply_elu_h<<<(int)((total2 + 255) / 256), 256>>>(p_HA, p_scale, p_shift, total2);
        } else {
            mma_gemm_t<true, false><<<ggrid, 256>>>(p_HB, WTs[l], bs[l], out_x, N, D);
        }
    }

    // 3. logits
    logits_kernel<<<(N + HEAD_ROWS - 1) / HEAD_ROWS, CC * HEAD_ROWS>>>(
        out_x, W_lin, b_lin, out_logits, N);
}